// round 1
// baseline (speedup 1.0000x reference)
#include <cuda_runtime.h>
#include <math.h>
#include <float.h>

#define MAXN 10016
#define KNN 16
#define NF 32

// Precomputed per-gaussian params (allocation-free scratch).
__device__ float4 g_mean4[MAXN];   // (mx, my, mz, 0)
__device__ float4 g_icov4[MAXN];   // (1/cov_x, 1/cov_y, 1/cov_z, 0)

__global__ void prep_kernel(const float* __restrict__ means,
                            const float* __restrict__ log_covs, int N) {
    int i = blockIdx.x * blockDim.x + threadIdx.x;
    if (i < N) {
        g_mean4[i] = make_float4(means[3*i], means[3*i+1], means[3*i+2], 0.f);
        g_icov4[i] = make_float4(expf(-log_covs[3*i]),
                                 expf(-log_covs[3*i+1]),
                                 expf(-log_covs[3*i+2]), 0.f);
    }
}

// One thread per query. All gaussian means staged in shared memory (160KB);
// every candidate read is a warp-broadcast LDS.128.
__global__ __launch_bounds__(256, 1)
void splash_kernel(const float* __restrict__ coords,
                   const float4* __restrict__ feats4,
                   float* __restrict__ out,
                   int M, int N) {
    extern __shared__ float4 sm[];
    for (int i = threadIdx.x; i < N; i += blockDim.x)
        sm[i] = g_mean4[i];
    __syncthreads();

    int q = blockIdx.x * blockDim.x + threadIdx.x;
    if (q >= M) return;

    const float cx = coords[3*q + 0];
    const float cy = coords[3*q + 1];
    const float cz = coords[3*q + 2];

    // Top-K as descending register array: bd[0] is the current worst (largest d2).
    float bd[KNN];
    int   bi[KNN];
#pragma unroll
    for (int t = 0; t < KNN; t++) { bd[t] = FLT_MAX; bi[t] = 0; }

#pragma unroll 4
    for (int j = 0; j < N; j++) {
        float4 m = sm[j];
        float dx = cx - m.x, dy = cy - m.y, dz = cz - m.z;
        float d2 = fmaf(dx, dx, fmaf(dy, dy, dz * dz));
        if (d2 < bd[0]) {
            bd[0] = d2; bi[0] = j;
            // single bubble pass restores descending order
#pragma unroll
            for (int t = 0; t < KNN - 1; t++) {
                bool p = bd[t] < bd[t+1];
                float hi = fmaxf(bd[t], bd[t+1]);
                float lo = fminf(bd[t], bd[t+1]);
                int ihi = p ? bi[t+1] : bi[t];
                int ilo = p ? bi[t]   : bi[t+1];
                bd[t] = hi; bd[t+1] = lo;
                bi[t] = ihi; bi[t+1] = ilo;
            }
        }
    }

    // Phase 2: gaussian weights + normalized feature aggregation.
    float acc[NF];
#pragma unroll
    for (int f = 0; f < NF; f++) acc[f] = 0.f;
    float wsum = 0.f;

#pragma unroll
    for (int t = 0; t < KNN; t++) {
        int id = bi[t];
        float4 mu = sm[id];
        float4 ic = g_icov4[id];
        float dx = cx - mu.x, dy = cy - mu.y, dz = cz - mu.z;
        float e = fmaf(dx*dx, ic.x, fmaf(dy*dy, ic.y, dz*dz*ic.z));
        float w = expf(-0.5f * e);
        wsum += w;
        const float4* fp = feats4 + (size_t)id * (NF/4);
#pragma unroll
        for (int c = 0; c < NF/4; c++) {
            float4 fv = fp[c];
            acc[4*c+0] = fmaf(w, fv.x, acc[4*c+0]);
            acc[4*c+1] = fmaf(w, fv.y, acc[4*c+1]);
            acc[4*c+2] = fmaf(w, fv.z, acc[4*c+2]);
            acc[4*c+3] = fmaf(w, fv.w, acc[4*c+3]);
        }
    }

    float inv = 1.f / (wsum + 1e-8f);
    float4* o4 = (float4*)(out + (size_t)q * NF);
#pragma unroll
    for (int c = 0; c < NF/4; c++)
        o4[c] = make_float4(acc[4*c+0]*inv, acc[4*c+1]*inv,
                            acc[4*c+2]*inv, acc[4*c+3]*inv);
}

extern "C" void kernel_launch(void* const* d_in, const int* in_sizes, int n_in,
                              void* d_out, int out_size) {
    const float* coords   = (const float*)d_in[0];
    const float* means    = (const float*)d_in[1];
    const float* log_covs = (const float*)d_in[2];
    const float* feats    = (const float*)d_in[3];
    float* out = (float*)d_out;

    int M = in_sizes[0] / 3;
    int N = in_sizes[1] / 3;

    prep_kernel<<<(N + 255) / 256, 256>>>(means, log_covs, N);

    size_t smem = (size_t)N * sizeof(float4);
    cudaFuncSetAttribute(splash_kernel,
                         cudaFuncAttributeMaxDynamicSharedMemorySize, (int)smem);
    splash_kernel<<<(M + 255) / 256, 256, smem>>>(coords, (const float4*)feats,
                                                  out, M, N);
}

// round 2
// speedup vs baseline: 5.2040x; 5.2040x over previous
#include <cuda_runtime.h>
#include <math.h>
#include <float.h>

#define G 8
#define NC (G*G*G)          // 512 cells
#define MAXN 10016
#define MAXM 32768
#define KNN 16
#define NF 32

// ---- device scratch (allocation-free) ----
__device__ float4 g_sorted[MAXN];       // cell-ordered gaussians: (x,y,z, orig-idx bits)
__device__ float4 g_icov_sorted[MAXN];  // cell-ordered inverse covariances
__device__ int g_cnt[NC];
__device__ int g_fill[NC];
__device__ int g_start[NC + 1];
__device__ int g_qcnt[NC];
__device__ int g_qfill[NC];
__device__ int g_qstart[NC + 1];
__device__ int g_qorder[MAXM];

__device__ __forceinline__ int cell_coord(float v) {
    int c = (int)(v * (float)G);
    return min(G - 1, max(0, c));
}

__global__ void k_clear() {
    int i = blockIdx.x * blockDim.x + threadIdx.x;
    if (i < NC) { g_cnt[i] = 0; g_fill[i] = 0; g_qcnt[i] = 0; g_qfill[i] = 0; }
}

__global__ void k_hist(const float* __restrict__ means, int N,
                       const float* __restrict__ coords, int M) {
    int i = blockIdx.x * blockDim.x + threadIdx.x;
    if (i < N) {
        int c = (cell_coord(means[3*i+2]) * G + cell_coord(means[3*i+1])) * G
                + cell_coord(means[3*i+0]);
        atomicAdd(&g_cnt[c], 1);
    }
    if (i < M) {
        int c = (cell_coord(coords[3*i+2]) * G + cell_coord(coords[3*i+1])) * G
                + cell_coord(coords[3*i+0]);
        atomicAdd(&g_qcnt[c], 1);
    }
}

__global__ void k_scan() {   // one block, NC threads: exclusive scans of both histograms
    __shared__ int s[NC];
    int t = threadIdx.x;
    s[t] = g_cnt[t];
    __syncthreads();
    for (int off = 1; off < NC; off <<= 1) {
        int v = (t >= off) ? s[t - off] : 0;
        __syncthreads();
        s[t] += v;
        __syncthreads();
    }
    g_start[t + 1] = s[t];
    if (t == 0) g_start[0] = 0;
    __syncthreads();
    s[t] = g_qcnt[t];
    __syncthreads();
    for (int off = 1; off < NC; off <<= 1) {
        int v = (t >= off) ? s[t - off] : 0;
        __syncthreads();
        s[t] += v;
        __syncthreads();
    }
    g_qstart[t + 1] = s[t];
    if (t == 0) g_qstart[0] = 0;
}

__global__ void k_scatter(const float* __restrict__ means,
                          const float* __restrict__ logc, int N,
                          const float* __restrict__ coords, int M) {
    int i = blockIdx.x * blockDim.x + threadIdx.x;
    if (i < N) {
        float mx = means[3*i], my = means[3*i+1], mz = means[3*i+2];
        int c = (cell_coord(mz) * G + cell_coord(my)) * G + cell_coord(mx);
        int pos = g_start[c] + atomicAdd(&g_fill[c], 1);
        g_sorted[pos] = make_float4(mx, my, mz, __int_as_float(i));
        g_icov_sorted[pos] = make_float4(expf(-logc[3*i]),
                                         expf(-logc[3*i+1]),
                                         expf(-logc[3*i+2]), 0.f);
    }
    if (i < M) {
        int c = (cell_coord(coords[3*i+2]) * G + cell_coord(coords[3*i+1])) * G
                + cell_coord(coords[3*i+0]);
        int pos = g_qstart[c] + atomicAdd(&g_qfill[c], 1);
        g_qorder[pos] = i;
    }
}

// Main kernel: one thread per (cell-sorted) query.
// Pass 1: grid-limited scan maintaining the 16 smallest distances (floats only,
//         cheap FMNMX bubble insert) with exact ring-expansion termination.
// Pass 2: rescan accepted window with threshold T to recover candidate slots.
// Phase 3: converged 16-wide weight+feature aggregation.
__global__ __launch_bounds__(224, 1)
void splash_main(const float* __restrict__ coords,
                 const float4* __restrict__ feats4,
                 float* __restrict__ out, int M, int N) {
    extern __shared__ char smraw[];
    float4* sm = (float4*)smraw;
    int* sstart = (int*)(smraw + sizeof(float4) * MAXN);

    for (int i = threadIdx.x; i < N; i += blockDim.x) sm[i] = g_sorted[i];
    for (int i = threadIdx.x; i <= NC; i += blockDim.x) sstart[i] = g_start[i];
    __syncthreads();

    int gt = blockIdx.x * blockDim.x + threadIdx.x;
    if (gt >= M) return;
    int q = g_qorder[gt];

    const float qx = coords[3*q+0], qy = coords[3*q+1], qz = coords[3*q+2];
    const int cx = cell_coord(qx), cy = cell_coord(qy), cz = cell_coord(qz);
    const float h = 1.0f / (float)G;

    float bd[KNN];          // descending: bd[0] = current 16th-smallest (worst kept)
#pragma unroll
    for (int t = 0; t < KNN; t++) bd[t] = FLT_MAX;

    int rfin = 1;
    for (int r = 1; r <= G; ++r) {
        rfin = r;
        // r==1: full 3^3 block. r>1: Chebyshev shell only (no double counting).
        for (int dz = -r; dz <= r; ++dz) {
            int z = cz + dz; if ((unsigned)z >= G) continue;
            for (int dy = -r; dy <= r; ++dy) {
                int y = cy + dy; if ((unsigned)y >= G) continue;
                bool edge = (dz == -r) | (dz == r) | (dy == -r) | (dy == r);
                int step = (r > 1 && !edge) ? 2 * r : 1;
                for (int dx = -r; dx <= r; dx += step) {
                    int x = cx + dx; if ((unsigned)x >= G) continue;
                    int cid = (z * G + y) * G + x;
                    int c0 = sstart[cid], c1 = sstart[cid + 1];
                    for (int c = c0; c < c1; ++c) {
                        float4 g = sm[c];
                        float ddx = qx - g.x, ddy = qy - g.y, ddz = qz - g.z;
                        float d2 = fmaf(ddx, ddx, fmaf(ddy, ddy, ddz * ddz));
                        if (d2 < bd[0]) {
                            bd[0] = d2;
#pragma unroll
                            for (int t = 0; t < KNN - 1; t++) {
                                float a = fmaxf(bd[t], bd[t + 1]);
                                float b = fminf(bd[t], bd[t + 1]);
                                bd[t] = a; bd[t + 1] = b;
                            }
                        }
                    }
                }
            }
        }
        // Exact termination: closest possible unscanned point lies beyond the
        // nearest un-clipped window face.
        float m = 1e30f;
        if (cx - r > 0)     m = fminf(m, qx - (float)(cx - r) * h);
        if (cx + r < G - 1) m = fminf(m, (float)(cx + r + 1) * h - qx);
        if (cy - r > 0)     m = fminf(m, qy - (float)(cy - r) * h);
        if (cy + r < G - 1) m = fminf(m, (float)(cy + r + 1) * h - qy);
        if (cz - r > 0)     m = fminf(m, qz - (float)(cz - r) * h);
        if (cz + r < G - 1) m = fminf(m, (float)(cz + r + 1) * h - qz);
        if (bd[0] <= m * m) break;
    }
    const float T = bd[0];

    // Pass 2: recover the 16 accepted slots (identical d2 expression).
    int myp[KNN];
#pragma unroll
    for (int t = 0; t < KNN; t++) myp[t] = 0;
    int cnt = 0;
    {
        const int r = rfin;
        for (int dz = -r; dz <= r; ++dz) {
            int z = cz + dz; if ((unsigned)z >= G) continue;
            for (int dy = -r; dy <= r; ++dy) {
                int y = cy + dy; if ((unsigned)y >= G) continue;
                for (int dx = -r; dx <= r; ++dx) {
                    int x = cx + dx; if ((unsigned)x >= G) continue;
                    int cid = (z * G + y) * G + x;
                    int c0 = sstart[cid], c1 = sstart[cid + 1];
                    for (int c = c0; c < c1; ++c) {
                        float4 g = sm[c];
                        float ddx = qx - g.x, ddy = qy - g.y, ddz = qz - g.z;
                        float d2 = fmaf(ddx, ddx, fmaf(ddy, ddy, ddz * ddz));
                        if (d2 <= T && cnt < KNN) { myp[cnt] = c; cnt++; }
                    }
                }
            }
        }
    }

    // Phase 3: converged aggregation (all lanes run all 16 iterations).
    float acc[NF];
#pragma unroll
    for (int f = 0; f < NF; f++) acc[f] = 0.f;
    float wsum = 0.f;
#pragma unroll
    for (int t = 0; t < KNN; t++) {
        int p = myp[t];
        float4 g = sm[p];
        float4 ic = g_icov_sorted[p];
        int id = __float_as_int(g.w);
        float ddx = qx - g.x, ddy = qy - g.y, ddz = qz - g.z;
        float e = fmaf(ddx * ddx, ic.x, fmaf(ddy * ddy, ic.y, ddz * ddz * ic.z));
        float w = __expf(-0.5f * e);
        wsum += w;
        const float4* fp = feats4 + (size_t)id * (NF / 4);
#pragma unroll
        for (int cc = 0; cc < NF / 4; cc++) {
            float4 fv = fp[cc];
            acc[4*cc+0] = fmaf(w, fv.x, acc[4*cc+0]);
            acc[4*cc+1] = fmaf(w, fv.y, acc[4*cc+1]);
            acc[4*cc+2] = fmaf(w, fv.z, acc[4*cc+2]);
            acc[4*cc+3] = fmaf(w, fv.w, acc[4*cc+3]);
        }
    }
    float inv = 1.f / (wsum + 1e-8f);
    float4* o4 = (float4*)(out + (size_t)q * NF);
#pragma unroll
    for (int cc = 0; cc < NF / 4; cc++)
        o4[cc] = make_float4(acc[4*cc+0] * inv, acc[4*cc+1] * inv,
                             acc[4*cc+2] * inv, acc[4*cc+3] * inv);
}

extern "C" void kernel_launch(void* const* d_in, const int* in_sizes, int n_in,
                              void* d_out, int out_size) {
    const float* coords = (const float*)d_in[0];
    const float* means  = (const float*)d_in[1];
    const float* logc   = (const float*)d_in[2];
    const float* feats  = (const float*)d_in[3];
    float* out = (float*)d_out;

    int M = in_sizes[0] / 3;
    int N = in_sizes[1] / 3;

    k_clear<<<(NC + 255) / 256, 256>>>();
    int mx = (M > N ? M : N);
    k_hist<<<(mx + 255) / 256, 256>>>(means, N, coords, M);
    k_scan<<<1, NC>>>();
    k_scatter<<<(mx + 255) / 256, 256>>>(means, logc, N, coords, M);

    size_t sh = sizeof(float4) * MAXN + sizeof(int) * (NC + 1);
    cudaFuncSetAttribute(splash_main,
                         cudaFuncAttributeMaxDynamicSharedMemorySize, (int)sh);
    splash_main<<<(M + 223) / 224, 224, sh>>>(coords, (const float4*)feats,
                                              out, M, N);
}

// round 3
// speedup vs baseline: 6.4092x; 1.2316x over previous
#include <cuda_runtime.h>
#include <math.h>
#include <float.h>

#define G 8
#define NC (G*G*G)
#define MAXN 10016
#define MAXM 32768
#define KNN 16
#define NF 32
#define CAP 1280            // 27-cell window capacity (avg ~527, worst ~700)

// ---- device scratch (allocation-free) ----
__device__ float4 g_sorted[MAXN];   // cell-ordered: (x,y,z, orig-idx bits)
__device__ float4 g_icov[MAXN];     // cell-ordered inverse covariances
__device__ int g_cnt[NC], g_fill[NC], g_start[NC + 1];
__device__ int g_qcnt[NC], g_qfill[NC], g_qstart[NC + 1];
__device__ int g_qorder[MAXM];

__device__ __forceinline__ int cell_coord(float v) {
    int c = (int)(v * (float)G);
    return min(G - 1, max(0, c));
}

__global__ void k_clear() {
    int i = blockIdx.x * blockDim.x + threadIdx.x;
    if (i < NC) { g_cnt[i] = 0; g_fill[i] = 0; g_qcnt[i] = 0; g_qfill[i] = 0; }
}

__global__ void k_hist(const float* __restrict__ means, int N,
                       const float* __restrict__ coords, int M) {
    int i = blockIdx.x * blockDim.x + threadIdx.x;
    if (i < N) {
        int c = (cell_coord(means[3*i+2]) * G + cell_coord(means[3*i+1])) * G
                + cell_coord(means[3*i+0]);
        atomicAdd(&g_cnt[c], 1);
    }
    if (i < M) {
        int c = (cell_coord(coords[3*i+2]) * G + cell_coord(coords[3*i+1])) * G
                + cell_coord(coords[3*i+0]);
        atomicAdd(&g_qcnt[c], 1);
    }
}

// shfl-based two-level exclusive scan of both 512-entry histograms
__global__ void k_scan() {
    __shared__ int ws[16];
    int t = threadIdx.x, lane = t & 31, w = t >> 5;

    int s = g_cnt[t];
    for (int o = 1; o < 32; o <<= 1) {
        int u = __shfl_up_sync(0xffffffffu, s, o);
        if (lane >= o) s += u;
    }
    if (lane == 31) ws[w] = s;
    __syncthreads();
    if (t < 32) {
        int v = (t < 16) ? ws[t] : 0;
        for (int o = 1; o < 16; o <<= 1) {
            int u = __shfl_up_sync(0xffffffffu, v, o);
            if (t >= o) v += u;
        }
        if (t < 16) ws[t] = v;
    }
    __syncthreads();
    g_start[t + 1] = (w ? ws[w - 1] : 0) + s;
    if (t == 0) g_start[0] = 0;
    __syncthreads();

    s = g_qcnt[t];
    for (int o = 1; o < 32; o <<= 1) {
        int u = __shfl_up_sync(0xffffffffu, s, o);
        if (lane >= o) s += u;
    }
    if (lane == 31) ws[w] = s;
    __syncthreads();
    if (t < 32) {
        int v = (t < 16) ? ws[t] : 0;
        for (int o = 1; o < 16; o <<= 1) {
            int u = __shfl_up_sync(0xffffffffu, v, o);
            if (t >= o) v += u;
        }
        if (t < 16) ws[t] = v;
    }
    __syncthreads();
    g_qstart[t + 1] = (w ? ws[w - 1] : 0) + s;
    if (t == 0) g_qstart[0] = 0;
}

__global__ void k_scatter(const float* __restrict__ means,
                          const float* __restrict__ logc, int N,
                          const float* __restrict__ coords, int M) {
    int i = blockIdx.x * blockDim.x + threadIdx.x;
    if (i < N) {
        float mx = means[3*i], my = means[3*i+1], mz = means[3*i+2];
        int c = (cell_coord(mz) * G + cell_coord(my)) * G + cell_coord(mx);
        int pos = g_start[c] + atomicAdd(&g_fill[c], 1);
        g_sorted[pos] = make_float4(mx, my, mz, __int_as_float(i));
        g_icov[pos] = make_float4(expf(-logc[3*i]), expf(-logc[3*i+1]),
                                  expf(-logc[3*i+2]), 0.f);
    }
    if (i < M) {
        int c = (cell_coord(coords[3*i+2]) * G + cell_coord(coords[3*i+1])) * G
                + cell_coord(coords[3*i+0]);
        int pos = g_qstart[c] + atomicAdd(&g_qfill[c], 1);
        g_qorder[pos] = i;
    }
}

// Exact per-query fallback (rare): full ring expansion from gmem, then
// threshold rescan, then aggregation. Same math as the main path.
__device__ __noinline__ void fallback_query(int q, float qx, float qy, float qz,
                                            int cx, int cy, int cz,
                                            const float4* __restrict__ feats4,
                                            float* __restrict__ out) {
    const float h = 1.0f / (float)G;
    float bd[KNN];
#pragma unroll
    for (int t = 0; t < KNN; t++) bd[t] = FLT_MAX;

    int rfin = 1;
    for (int r = 1; r <= G; ++r) {
        rfin = r;
        for (int dz = -r; dz <= r; ++dz) {
            int z = cz + dz; if ((unsigned)z >= G) continue;
            for (int dy = -r; dy <= r; ++dy) {
                int y = cy + dy; if ((unsigned)y >= G) continue;
                bool edge = (dz == -r) | (dz == r) | (dy == -r) | (dy == r);
                int step = (r > 1 && !edge) ? 2 * r : 1;
                for (int dx = -r; dx <= r; dx += step) {
                    int x = cx + dx; if ((unsigned)x >= G) continue;
                    int cid = (z * G + y) * G + x;
                    int c0 = g_start[cid], c1 = g_start[cid + 1];
                    for (int c = c0; c < c1; ++c) {
                        float4 g = g_sorted[c];
                        float ddx = qx - g.x, ddy = qy - g.y, ddz = qz - g.z;
                        float d2 = fmaf(ddx, ddx, fmaf(ddy, ddy, ddz * ddz));
                        if (d2 < bd[0]) {
                            bd[0] = d2;
#pragma unroll
                            for (int t = 0; t < KNN - 1; t++) {
                                float a = fmaxf(bd[t], bd[t+1]);
                                float b = fminf(bd[t], bd[t+1]);
                                bd[t] = a; bd[t+1] = b;
                            }
                        }
                    }
                }
            }
        }
        float m = 1e30f;
        if (cx - r > 0)     m = fminf(m, qx - (float)(cx - r) * h);
        if (cx + r < G - 1) m = fminf(m, (float)(cx + r + 1) * h - qx);
        if (cy - r > 0)     m = fminf(m, qy - (float)(cy - r) * h);
        if (cy + r < G - 1) m = fminf(m, (float)(cy + r + 1) * h - qy);
        if (cz - r > 0)     m = fminf(m, qz - (float)(cz - r) * h);
        if (cz + r < G - 1) m = fminf(m, (float)(cz + r + 1) * h - qz);
        if (bd[0] <= m * m) break;
    }
    const float T = bd[0];

    int myp[KNN];
#pragma unroll
    for (int t = 0; t < KNN; t++) myp[t] = 0;
    int cnt = 0;
    {
        const int r = rfin;
        for (int dz = -r; dz <= r; ++dz) {
            int z = cz + dz; if ((unsigned)z >= G) continue;
            for (int dy = -r; dy <= r; ++dy) {
                int y = cy + dy; if ((unsigned)y >= G) continue;
                for (int dx = -r; dx <= r; ++dx) {
                    int x = cx + dx; if ((unsigned)x >= G) continue;
                    int cid = (z * G + y) * G + x;
                    int c0 = g_start[cid], c1 = g_start[cid + 1];
                    for (int c = c0; c < c1; ++c) {
                        float4 g = g_sorted[c];
                        float ddx = qx - g.x, ddy = qy - g.y, ddz = qz - g.z;
                        float d2 = fmaf(ddx, ddx, fmaf(ddy, ddy, ddz * ddz));
                        if (d2 <= T && cnt < KNN) { myp[cnt] = c; cnt++; }
                    }
                }
            }
        }
    }

    float acc[NF];
#pragma unroll
    for (int f = 0; f < NF; f++) acc[f] = 0.f;
    float wsum = 0.f;
#pragma unroll
    for (int t = 0; t < KNN; t++) {
        int p = myp[t];
        float4 g = g_sorted[p];
        float4 ic = g_icov[p];
        int id = __float_as_int(g.w);
        float ddx = qx - g.x, ddy = qy - g.y, ddz = qz - g.z;
        float e = fmaf(ddx*ddx, ic.x, fmaf(ddy*ddy, ic.y, ddz*ddz*ic.z));
        float wgt = __expf(-0.5f * e);
        wsum += wgt;
        const float4* fp = feats4 + (size_t)id * (NF/4);
#pragma unroll
        for (int cc = 0; cc < NF/4; cc++) {
            float4 fv = fp[cc];
            acc[4*cc+0] = fmaf(wgt, fv.x, acc[4*cc+0]);
            acc[4*cc+1] = fmaf(wgt, fv.y, acc[4*cc+1]);
            acc[4*cc+2] = fmaf(wgt, fv.z, acc[4*cc+2]);
            acc[4*cc+3] = fmaf(wgt, fv.w, acc[4*cc+3]);
        }
    }
    float inv = 1.f / (wsum + 1e-8f);
    float4* o4 = (float4*)(out + (size_t)q * NF);
#pragma unroll
    for (int cc = 0; cc < NF/4; cc++)
        o4[cc] = make_float4(acc[4*cc+0]*inv, acc[4*cc+1]*inv,
                             acc[4*cc+2]*inv, acc[4*cc+3]*inv);
}

// One block per cell. The 27-cell gaussian window lives in 40KB smem
// (positions + inverse covariances), 5 blocks/SM.
__global__ __launch_bounds__(128, 5)
void splash_cell(const float* __restrict__ coords,
                 const float4* __restrict__ feats4,
                 float* __restrict__ out) {
    __shared__ float4 spos[CAP];
    __shared__ float4 sicv[CAP];

    const int cell = blockIdx.x;
    const int q0 = g_qstart[cell], q1 = g_qstart[cell + 1];
    if (q0 == q1) return;

    const int cx = cell & 7, cy = (cell >> 3) & 7, cz = cell >> 6;
    const int x0 = max(cx - 1, 0), x1e = min(cx + 1, G - 1) + 1;

    // Cooperative window copy: x-adjacent cells are contiguous in g_sorted,
    // so each (z,y) row is one coalesced range. All threads compute identical
    // offsets; copies are thread-strided.
    int nS = 0;
    bool ovf = false;
    for (int z = max(cz - 1, 0); z <= min(cz + 1, G - 1); ++z) {
        for (int y = max(cy - 1, 0); y <= min(cy + 1, G - 1); ++y) {
            int base = (z * G + y) * G;
            int r0 = g_start[base + x0];
            int r1 = g_start[base + x1e];
            int len = r1 - r0;
            if (ovf || nS + len > CAP) { ovf = true; continue; }
            for (int i = threadIdx.x; i < len; i += blockDim.x) {
                spos[nS + i] = g_sorted[r0 + i];
                sicv[nS + i] = g_icov[r0 + i];
            }
            nS += len;
        }
    }
    __syncthreads();

    const float h = 1.0f / (float)G;

    for (int qi = q0 + threadIdx.x; qi < q1; qi += blockDim.x) {
        const int q = g_qorder[qi];
        const float qx = coords[3*q+0], qy = coords[3*q+1], qz = coords[3*q+2];

        if (ovf) { fallback_query(q, qx, qy, qz, cx, cy, cz, feats4, out); continue; }

        // Pass 1: 16 smallest distances over the smem window.
        float bd[KNN];
#pragma unroll
        for (int t = 0; t < KNN; t++) bd[t] = FLT_MAX;

#pragma unroll 4
        for (int j = 0; j < nS; ++j) {
            float4 g = spos[j];
            float ddx = qx - g.x, ddy = qy - g.y, ddz = qz - g.z;
            float d2 = fmaf(ddx, ddx, fmaf(ddy, ddy, ddz * ddz));
            if (d2 < bd[0]) {
                bd[0] = d2;
#pragma unroll
                for (int t = 0; t < KNN - 1; t++) {
                    float a = fmaxf(bd[t], bd[t+1]);
                    float b = fminf(bd[t], bd[t+1]);
                    bd[t] = a; bd[t+1] = b;
                }
            }
        }

        // Exact r=1 termination test (clipped faces have nothing beyond them).
        float m = 1e30f;
        if (cx - 1 > 0)     m = fminf(m, qx - (float)(cx - 1) * h);
        if (cx + 1 < G - 1) m = fminf(m, (float)(cx + 2) * h - qx);
        if (cy - 1 > 0)     m = fminf(m, qy - (float)(cy - 1) * h);
        if (cy + 1 < G - 1) m = fminf(m, (float)(cy + 2) * h - qy);
        if (cz - 1 > 0)     m = fminf(m, qz - (float)(cz - 1) * h);
        if (cz + 1 < G - 1) m = fminf(m, (float)(cz + 2) * h - qz);
        if (bd[0] > m * m) {
            fallback_query(q, qx, qy, qz, cx, cy, cz, feats4, out);
            continue;
        }
        const float T = bd[0];

        // Pass 2: recover accepted slots.
        int myp[KNN];
#pragma unroll
        for (int t = 0; t < KNN; t++) myp[t] = 0;
        int cnt = 0;
#pragma unroll 4
        for (int j = 0; j < nS; ++j) {
            float4 g = spos[j];
            float ddx = qx - g.x, ddy = qy - g.y, ddz = qz - g.z;
            float d2 = fmaf(ddx, ddx, fmaf(ddy, ddy, ddz * ddz));
            if (d2 <= T && cnt < KNN) { myp[cnt] = j; cnt++; }
        }

        // Aggregation (converged, fully unrolled).
        float acc[NF];
#pragma unroll
        for (int f = 0; f < NF; f++) acc[f] = 0.f;
        float wsum = 0.f;
#pragma unroll
        for (int t = 0; t < KNN; t++) {
            int p = myp[t];
            float4 g = spos[p];
            float4 ic = sicv[p];
            int id = __float_as_int(g.w);
            float ddx = qx - g.x, ddy = qy - g.y, ddz = qz - g.z;
            float e = fmaf(ddx*ddx, ic.x, fmaf(ddy*ddy, ic.y, ddz*ddz*ic.z));
            float wgt = __expf(-0.5f * e);
            wsum += wgt;
            const float4* fp = feats4 + (size_t)id * (NF/4);
#pragma unroll
            for (int cc = 0; cc < NF/4; cc++) {
                float4 fv = fp[cc];
                acc[4*cc+0] = fmaf(wgt, fv.x, acc[4*cc+0]);
                acc[4*cc+1] = fmaf(wgt, fv.y, acc[4*cc+1]);
                acc[4*cc+2] = fmaf(wgt, fv.z, acc[4*cc+2]);
                acc[4*cc+3] = fmaf(wgt, fv.w, acc[4*cc+3]);
            }
        }
        float inv = 1.f / (wsum + 1e-8f);
        float4* o4 = (float4*)(out + (size_t)q * NF);
#pragma unroll
        for (int cc = 0; cc < NF/4; cc++)
            o4[cc] = make_float4(acc[4*cc+0]*inv, acc[4*cc+1]*inv,
                                 acc[4*cc+2]*inv, acc[4*cc+3]*inv);
    }
}

extern "C" void kernel_launch(void* const* d_in, const int* in_sizes, int n_in,
                              void* d_out, int out_size) {
    const float* coords = (const float*)d_in[0];
    const float* means  = (const float*)d_in[1];
    const float* logc   = (const float*)d_in[2];
    const float* feats  = (const float*)d_in[3];
    float* out = (float*)d_out;

    int M = in_sizes[0] / 3;
    int N = in_sizes[1] / 3;
    int mx = (M > N ? M : N);

    k_clear<<<(NC + 255) / 256, 256>>>();
    k_hist<<<(mx + 255) / 256, 256>>>(means, N, coords, M);
    k_scan<<<1, NC>>>();
    k_scatter<<<(mx + 255) / 256, 256>>>(means, logc, N, coords, M);
    splash_cell<<<NC, 128>>>(coords, (const float4*)feats, out);
}